// round 9
// baseline (speedup 1.0000x reference)
#include <cuda_runtime.h>
#include <stdint.h>

#define D 8
#define DD 64

// Grid-stride float4 zero fill: pure HBM-write-bound (measured ~6.7 TB/s).
__global__ void zero_kernel(float4* __restrict__ out, size_t n4) {
    size_t i = (size_t)blockIdx.x * blockDim.x + threadIdx.x;
    size_t stride = (size_t)gridDim.x * blockDim.x;
    const float4 z = make_float4(0.f, 0.f, 0.f, 0.f);
    for (; i < n4; i += stride) out[i] = z;
}

// One edge per 16-thread group, one group-iteration per thread — no loop, no
// barrier. W rows 4q..4q+3 held in registers (L1-hot prologue). All 32K edge
// load chains are independent -> DRAM latency hidden by MLP. Duplicate
// (src,dst) edges write identical values, so races are benign/deterministic.
__global__ void __launch_bounds__(256) scatter_kernel(
        const float* __restrict__ x,
        const int* __restrict__ ei,
        const float* __restrict__ W,
        float4* __restrict__ out4,
        int e, int n) {
    int t = threadIdx.x;
    int q = t & 15;                          // output rows 4q .. 4q+3
    int edge = blockIdx.x * 16 + (t >> 4);
    if (edge >= e) return;

    // Issue the edge/feature loads FIRST (long-latency, off critical path of W).
    int src = __ldg(&ei[edge]);
    int dst = __ldg(&ei[e + edge]);
    const float4* xs = (const float4*)(x + src * D);
    const float4* xd = (const float4*)(x + dst * D);
    float4 a0 = __ldg(xs), a1 = __ldg(xs + 1);
    float4 b0 = __ldg(xd), b1 = __ldg(xd + 1);

    // W rows for this thread (L1-hot after first block on each SM).
    float4 w[8];
    #pragma unroll
    for (int c = 0; c < 4; c++) {
        const float4* wp = (const float4*)(W + (q * 4 + c) * D);
        w[2 * c]     = __ldg(wp);
        w[2 * c + 1] = __ldg(wp + 1);
    }

    float dv[D];
    dv[0] = fabsf(a0.x - b0.x); dv[1] = fabsf(a0.y - b0.y);
    dv[2] = fabsf(a0.z - b0.z); dv[3] = fabsf(a0.w - b0.w);
    dv[4] = fabsf(a1.x - b1.x); dv[5] = fabsf(a1.y - b1.y);
    dv[6] = fabsf(a1.z - b1.z); dv[7] = fabsf(a1.w - b1.w);

    float acc[4];
    #pragma unroll
    for (int c = 0; c < 4; c++) {
        acc[c] = w[2*c].x   * dv[0] + w[2*c].y   * dv[1]
               + w[2*c].z   * dv[2] + w[2*c].w   * dv[3]
               + w[2*c+1].x * dv[4] + w[2*c+1].y * dv[5]
               + w[2*c+1].z * dv[6] + w[2*c+1].w * dv[7];
    }

    size_t cell = (size_t)src * n + dst;
    out4[cell * 16 + q] = make_float4(acc[0], acc[1], acc[2], acc[3]);
}

extern "C" void kernel_launch(void* const* d_in, const int* in_sizes, int n_in,
                              void* d_out, int out_size) {
    const float* x  = (const float*)d_in[0];
    const int*   ei = (const int*)d_in[1];    // int64 in reference, int32 here
    const float* W  = (const float*)d_in[2];

    int n = in_sizes[0] / D;     // 1024
    int e = in_sizes[1] / 2;     // 32768

    size_t n4 = (size_t)out_size / 4;   // out_size = n*n*64 floats
    zero_kernel<<<4096, 256>>>((float4*)d_out, n4);

    // 16 edges per 256-thread block, one edge per 16-thread group.
    scatter_kernel<<<(e + 15) / 16, 256>>>(x, ei, W, (float4*)d_out, e, n);
}

// round 10
// speedup vs baseline: 1.1978x; 1.1978x over previous
#include <cuda_runtime.h>
#include <stdint.h>

#define D 8
#define DD 64

// Grid-stride float4 zero fill: pure HBM-write-bound (measured ~6.7 TB/s).
__global__ void zero_kernel(float4* __restrict__ out, size_t n4) {
    size_t i = (size_t)blockIdx.x * blockDim.x + threadIdx.x;
    size_t stride = (size_t)gridDim.x * blockDim.x;
    const float4 z = make_float4(0.f, 0.f, 0.f, 0.f);
    for (; i < n4; i += stride) out[i] = z;
}

// 16-thread group handles 4 consecutive edges. W rows 4q..4q+3 live in
// registers for the whole kernel (amortized over 4 edges). All 4 edges'
// index + feature loads are issued up front (MLP=16) before any compute, so
// post-zero-pass DRAM misses overlap instead of chaining. Duplicate
// (src,dst) edges write identical values -> races benign/deterministic.
__global__ void __launch_bounds__(256) scatter_kernel(
        const float* __restrict__ x,
        const int* __restrict__ ei,
        const float* __restrict__ W,
        float4* __restrict__ out4,
        int e, int n) {
    int t = threadIdx.x;
    int q = t & 15;                          // output rows 4q .. 4q+3
    int group = blockIdx.x * 16 + (t >> 4);  // 4 edges per group
    int ebase = group * 4;
    if (ebase >= e) return;

    // Edge indices: two vector loads (e % 4 == 0 in this dataset; guarded).
    int4 s4, d4;
    if (ebase + 3 < e && ((e & 3) == 0)) {
        s4 = __ldg((const int4*)(ei + ebase));
        d4 = __ldg((const int4*)(ei + e + ebase));
    } else {
        int se[4], de[4];
        #pragma unroll
        for (int j = 0; j < 4; j++) {
            int eg = min(ebase + j, e - 1);
            se[j] = __ldg(&ei[eg]); de[j] = __ldg(&ei[e + eg]);
        }
        s4 = make_int4(se[0], se[1], se[2], se[3]);
        d4 = make_int4(de[0], de[1], de[2], de[3]);
    }
    int src[4] = {s4.x, s4.y, s4.z, s4.w};
    int dst[4] = {d4.x, d4.y, d4.z, d4.w};

    // Issue ALL feature loads up front — 16 independent LDG.128.
    float4 a0[4], a1[4], b0[4], b1[4];
    #pragma unroll
    for (int j = 0; j < 4; j++) {
        const float4* xs = (const float4*)(x + src[j] * D);
        const float4* xd = (const float4*)(x + dst[j] * D);
        a0[j] = __ldg(xs); a1[j] = __ldg(xs + 1);
        b0[j] = __ldg(xd); b1[j] = __ldg(xd + 1);
    }

    // W rows for this thread (L1-hot, loaded once per thread).
    float4 w[8];
    #pragma unroll
    for (int c = 0; c < 4; c++) {
        const float4* wp = (const float4*)(W + (q * 4 + c) * D);
        w[2 * c]     = __ldg(wp);
        w[2 * c + 1] = __ldg(wp + 1);
    }

    #pragma unroll
    for (int j = 0; j < 4; j++) {
        if (ebase + j >= e) break;
        float dv[D];
        dv[0] = fabsf(a0[j].x - b0[j].x); dv[1] = fabsf(a0[j].y - b0[j].y);
        dv[2] = fabsf(a0[j].z - b0[j].z); dv[3] = fabsf(a0[j].w - b0[j].w);
        dv[4] = fabsf(a1[j].x - b1[j].x); dv[5] = fabsf(a1[j].y - b1[j].y);
        dv[6] = fabsf(a1[j].z - b1[j].z); dv[7] = fabsf(a1[j].w - b1[j].w);

        float acc[4];
        #pragma unroll
        for (int c = 0; c < 4; c++) {
            acc[c] = w[2*c].x   * dv[0] + w[2*c].y   * dv[1]
                   + w[2*c].z   * dv[2] + w[2*c].w   * dv[3]
                   + w[2*c+1].x * dv[4] + w[2*c+1].y * dv[5]
                   + w[2*c+1].z * dv[6] + w[2*c+1].w * dv[7];
        }

        size_t cell = (size_t)src[j] * n + dst[j];
        out4[cell * 16 + q] = make_float4(acc[0], acc[1], acc[2], acc[3]);
    }
}

extern "C" void kernel_launch(void* const* d_in, const int* in_sizes, int n_in,
                              void* d_out, int out_size) {
    const float* x  = (const float*)d_in[0];
    const int*   ei = (const int*)d_in[1];    // int64 in reference, int32 here
    const float* W  = (const float*)d_in[2];

    int n = in_sizes[0] / D;     // 1024
    int e = in_sizes[1] / 2;     // 32768

    size_t n4 = (size_t)out_size / 4;   // out_size = n*n*64 floats
    zero_kernel<<<4096, 256>>>((float4*)d_out, n4);

    // 8192 groups of 16 threads, 4 edges each.
    int ngroups = (e + 3) / 4;
    scatter_kernel<<<(ngroups + 15) / 16, 256>>>(x, ei, W, (float4*)d_out, e, n);
}